// round 16
// baseline (speedup 1.0000x reference)
#include <cuda_runtime.h>
#include <cuda_bf16.h>

// gene_seq (N=256, M=2000) int32 in [0,4); embedding_mat (M=2000, 4, D=128) f32.
// out[n, m, :] = embedding_mat[m, gene_seq[n,m], :] / max(||row||, 1e-12)
//
// STG.256 variant: each HALF-WARP holds a duplicated full copy of the warp's
// 4 candidate rows (8 floats per lane per row). Each inner-loop iteration
// stores TWO n-rows per warp using one st.global.cs.v8.f32 (256-bit) per
// lane — half the store transactions of the STG.128 design, same bytes.
// Shape otherwise identical to best (MTILE=8, 256 thr, grid (250,4), .cs).

#define NM 256
#define MM 2000
#define DD 128
#define MTILE 8
#define NTILE 64
#define THREADS 256
#define ROW_F4 (DD / 4)   // 32 float4 per row

__device__ __forceinline__ float4 sel4(int g, const float4& r0, const float4& r1,
                                       const float4& r2, const float4& r3) {
    int hi = g >> 1, lo = g & 1;
    float4 ta, tb, v;
    ta.x = lo ? r1.x : r0.x;  tb.x = lo ? r3.x : r2.x;  v.x = hi ? tb.x : ta.x;
    ta.y = lo ? r1.y : r0.y;  tb.y = lo ? r3.y : r2.y;  v.y = hi ? tb.y : ta.y;
    ta.z = lo ? r1.z : r0.z;  tb.z = lo ? r3.z : r2.z;  v.z = hi ? tb.z : ta.z;
    ta.w = lo ? r1.w : r0.w;  tb.w = lo ? r3.w : r2.w;  v.w = hi ? tb.w : ta.w;
    return v;
}

__device__ __forceinline__ void stcs8(float* p, float4 a, float4 b) {
    asm volatile("st.global.cs.v8.f32 [%0], {%1,%2,%3,%4,%5,%6,%7,%8};"
                 :: "l"(p), "f"(a.x), "f"(a.y), "f"(a.z), "f"(a.w),
                    "f"(b.x), "f"(b.y), "f"(b.z), "f"(b.w) : "memory");
}

__global__ void __launch_bounds__(THREADS) embed_kernel(
    const int* __restrict__ seq,
    const float* __restrict__ emb,
    float* __restrict__ out)
{
    __shared__ int sseq[NTILE][MTILE];   // 2 KB

    const int m0   = blockIdx.x * MTILE;
    const int n0   = blockIdx.y * NTILE;
    const int tid  = threadIdx.x;
    const int warp = tid >> 5;
    const int lane = tid & 31;
    const int hl   = lane & 15;          // lane within half-warp
    const int h    = lane >> 4;          // which half (0/1)
    const int m    = m0 + warp;

    // --- stage seq tile: seq[n0+j][m0+mm], 64x8 ints ---
    #pragma unroll
    for (int i = 0; i < (NTILE * MTILE) / THREADS; i++) {
        int t  = tid + i * THREADS;
        int j  = t >> 3;
        int mm = t & 7;
        sseq[j][mm] = __ldg(seq + (size_t)(n0 + j) * MM + m0 + mm);
    }

    // --- each half-warp loads a full copy of the 4 candidate rows ---
    // lane holds floats [hl*8, hl*8+8) of each row as two float4 (A = first, B = second)
    const float4* src = reinterpret_cast<const float4*>(emb + (size_t)m * 4 * DD);
    float4 a0 = __ldg(src + 0 * ROW_F4 + 2 * hl);
    float4 b0 = __ldg(src + 0 * ROW_F4 + 2 * hl + 1);
    float4 a1 = __ldg(src + 1 * ROW_F4 + 2 * hl);
    float4 b1 = __ldg(src + 1 * ROW_F4 + 2 * hl + 1);
    float4 a2 = __ldg(src + 2 * ROW_F4 + 2 * hl);
    float4 b2 = __ldg(src + 2 * ROW_F4 + 2 * hl + 1);
    float4 a3 = __ldg(src + 3 * ROW_F4 + 2 * hl);
    float4 b3 = __ldg(src + 3 * ROW_F4 + 2 * hl + 1);

    // --- norms: reduce over the 16-lane half (each half holds the full row) ---
    float s0 = a0.x*a0.x + a0.y*a0.y + a0.z*a0.z + a0.w*a0.w
             + b0.x*b0.x + b0.y*b0.y + b0.z*b0.z + b0.w*b0.w;
    float s1 = a1.x*a1.x + a1.y*a1.y + a1.z*a1.z + a1.w*a1.w
             + b1.x*b1.x + b1.y*b1.y + b1.z*b1.z + b1.w*b1.w;
    float s2 = a2.x*a2.x + a2.y*a2.y + a2.z*a2.z + a2.w*a2.w
             + b2.x*b2.x + b2.y*b2.y + b2.z*b2.z + b2.w*b2.w;
    float s3 = a3.x*a3.x + a3.y*a3.y + a3.z*a3.z + a3.w*a3.w
             + b3.x*b3.x + b3.y*b3.y + b3.z*b3.z + b3.w*b3.w;
    #pragma unroll
    for (int off = 8; off > 0; off >>= 1) {   // xor stays within the 16-lane half
        s0 += __shfl_xor_sync(0xFFFFFFFFu, s0, off);
        s1 += __shfl_xor_sync(0xFFFFFFFFu, s1, off);
        s2 += __shfl_xor_sync(0xFFFFFFFFu, s2, off);
        s3 += __shfl_xor_sync(0xFFFFFFFFu, s3, off);
    }
    float c0 = 1.0f / fmaxf(sqrtf(s0), 1e-12f);
    float c1 = 1.0f / fmaxf(sqrtf(s1), 1e-12f);
    float c2 = 1.0f / fmaxf(sqrtf(s2), 1e-12f);
    float c3 = 1.0f / fmaxf(sqrtf(s3), 1e-12f);
    a0.x *= c0; a0.y *= c0; a0.z *= c0; a0.w *= c0;
    b0.x *= c0; b0.y *= c0; b0.z *= c0; b0.w *= c0;
    a1.x *= c1; a1.y *= c1; a1.z *= c1; a1.w *= c1;
    b1.x *= c1; b1.y *= c1; b1.z *= c1; b1.w *= c1;
    a2.x *= c2; a2.y *= c2; a2.z *= c2; a2.w *= c2;
    b2.x *= c2; b2.y *= c2; b2.z *= c2; b2.w *= c2;
    a3.x *= c3; a3.y *= c3; a3.z *= c3; a3.w *= c3;
    b3.x *= c3; b3.y *= c3; b3.z *= c3; b3.w *= c3;

    __syncthreads();   // sseq ready

    // --- stream outputs: 2 n-rows per warp per STG.256; 2 chains per iter ---
    // half h handles row j = 2*jj + h; lane stores floats [hl*8, hl*8+8).
    float* dstb = out + ((size_t)n0 * MM + m) * DD + hl * 8;
    const size_t nstrideF = (size_t)MM * DD;   // float stride between n's

    #pragma unroll 8
    for (int jj = 0; jj < 16; jj++) {
        int j1 = 2 * jj + h;
        int j2 = j1 + 32;
        int g1 = sseq[j1][warp];
        int g2 = sseq[j2][warp];
        float4 va = sel4(g1, a0, a1, a2, a3);
        float4 vb = sel4(g1, b0, b1, b2, b3);
        float4 wa = sel4(g2, a0, a1, a2, a3);
        float4 wb = sel4(g2, b0, b1, b2, b3);
        stcs8(dstb + (size_t)j1 * nstrideF, va, vb);
        stcs8(dstb + (size_t)j2 * nstrideF, wa, wb);
    }
}

extern "C" void kernel_launch(void* const* d_in, const int* in_sizes, int n_in,
                              void* d_out, int out_size) {
    const int*   seq = (const int*)d_in[0];     // (256, 2000) int32
    const float* emb = (const float*)d_in[1];   // (2000, 4, 128) f32
    float*       out = (float*)d_out;           // (256, 2000, 128) f32

    dim3 grid(MM / MTILE, NM / NTILE);          // (250, 4)
    embed_kernel<<<grid, THREADS>>>(seq, emb, out);
}